// round 3
// baseline (speedup 1.0000x reference)
#include <cuda_runtime.h>
#include <cstdint>

#define T_SEQ 2048
#define NB    64
#define DIN   256
#define NH    256

// scratch: precomputed input projection xw[t][b][h]  (128 MB, static — no allocs)
__device__ float g_xw[(size_t)T_SEQ * NB * NH];

// ---------------- packed fp32x2 helpers (sm_100+) ----------------
__device__ __forceinline__ unsigned long long fma2(unsigned long long a,
                                                   unsigned long long b,
                                                   unsigned long long c) {
    unsigned long long d;
    asm("fma.rn.f32x2 %0, %1, %2, %3;" : "=l"(d) : "l"(a), "l"(b), "l"(c));
    return d;
}
__device__ __forceinline__ float f2sum(unsigned long long v) {
    float lo, hi;
    asm("mov.b64 {%0, %1}, %2;" : "=f"(lo), "=f"(hi) : "l"(v));
    return lo + hi;
}
__device__ __forceinline__ unsigned long long packf2(float lo, float hi) {
    unsigned long long r;
    asm("mov.b64 %0, {%1, %2};" : "=l"(r) : "f"(lo), "f"(hi));
    return r;
}
__device__ __forceinline__ uint32_t smem_u32(const void* p) {
    uint32_t a;
    asm("{ .reg .u64 t; cvta.to.shared.u64 t, %1; cvt.u32.u64 %0, t; }"
        : "=r"(a) : "l"(p));
    return a;
}
__device__ __forceinline__ uint32_t mapa_(uint32_t addr, int rank) {
    uint32_t r;
    asm("mapa.shared::cluster.u32 %0, %1, %2;" : "=r"(r) : "r"(addr), "r"(rank));
    return r;
}
__device__ __forceinline__ void cluster_sync_() {
    asm volatile("barrier.cluster.arrive.aligned;\n\t"
                 "barrier.cluster.wait.aligned;" ::: "memory");
}
__device__ __forceinline__ void mbar_init(uint32_t addr, int cnt) {
    asm volatile("mbarrier.init.shared.b64 [%0], %1;" :: "r"(addr), "r"(cnt) : "memory");
}
__device__ __forceinline__ void mbar_arrive(uint32_t addr) {
    asm volatile("mbarrier.arrive.shared.b64 _, [%0];" :: "r"(addr) : "memory");
}
__device__ __forceinline__ void mbar_expect(uint32_t addr, int bytes) {
    asm volatile("mbarrier.arrive.expect_tx.shared.b64 _, [%0], %1;"
                 :: "r"(addr), "r"(bytes) : "memory");
}
// acquire(cta)-wait on local mbarrier for given phase parity (HW nap, no spin fence)
__device__ __forceinline__ void mbar_wait(uint32_t addr, int parity) {
    asm volatile(
        "{\n\t.reg .pred P;\n\t"
        "WLOOP%=:\n\t"
        "mbarrier.try_wait.parity.acquire.cta.shared::cta.b64 P, [%0], %1, 0x989680;\n\t"
        "@P bra WDONE%=;\n\t"
        "bra WLOOP%=;\n\t"
        "WDONE%=:\n\t}"
        :: "r"(addr), "r"(parity) : "memory");
}
// async store to (possibly remote) cluster smem; complete_tx on that CTA's mbarrier
__device__ __forceinline__ void st_async_b64(uint32_t addr, unsigned long long v,
                                             uint32_t mbar) {
    asm volatile(
        "st.async.shared::cluster.mbarrier::complete_tx::bytes.b64 [%0], %1, [%2];"
        :: "r"(addr), "l"(v), "r"(mbar) : "memory");
}

// =================================================================
// Kernel 1: input projection  g_xw[row][j] = x[row]·w_ih[j] + b_ih[j] + b_hh[j]
// (unchanged — fp32 issue-bound, ~270us)
// =================================================================
__global__ void __launch_bounds__(256, 1)
xw_kernel(const float* __restrict__ x,
          const float* __restrict__ w_ih,
          const float* __restrict__ b_ih,
          const float* __restrict__ b_hh) {
    __shared__ __align__(16) float xs[8][256];
    __shared__ float pbuf[8 * 512];

    const int tid  = threadIdx.x;
    const int w    = tid >> 5;
    const int lane = tid & 31;
    const int kg   = w >> 1;
    const int og   = ((w & 1) << 5) | lane;
    const int half = blockIdx.y;
    const int rowbase0 = blockIdx.x * 128;

    unsigned long long wa[32], wb[32];
    {
        const int j0 = half * 128 + og, j1 = j0 + 64;
        const unsigned long long* p0 =
            (const unsigned long long*)(w_ih + (size_t)j0 * DIN + kg * 64);
        const unsigned long long* p1 =
            (const unsigned long long*)(w_ih + (size_t)j1 * DIN + kg * 64);
#pragma unroll
        for (int i = 0; i < 32; i++) { wa[i] = p0[i]; wb[i] = p1[i]; }
    }
    float bias = 0.f;
    if (tid < 128) bias = b_ih[half * 128 + tid] + b_hh[half * 128 + tid];

    const float4* xg = (const float4*)x;
    {
        int q = tid, r = q >> 6, c4 = q & 63;
        ((float4*)xs)[q]       = xg[(size_t)(rowbase0 + r) * 64 + c4];
        ((float4*)xs)[q + 256] = xg[(size_t)(rowbase0 + 4 + r) * 64 + c4];
    }
    __syncthreads();

    for (int it = 0; it < 16; it++) {
        const int rowbase = rowbase0 + it * 8;
        float4 n0, n1;
        if (it < 15) {
            int q = tid, r = q >> 6, c4 = q & 63;
            int nrb = rowbase + 8;
            n0 = xg[(size_t)(nrb + r) * 64 + c4];
            n1 = xg[(size_t)(nrb + 4 + r) * 64 + c4];
        }
        unsigned long long acc[8][2];
#pragma unroll
        for (int r = 0; r < 8; r++) { acc[r][0] = 0ull; acc[r][1] = 0ull; }
#pragma unroll
        for (int r = 0; r < 8; r++) {
            const ulonglong2* xp = (const ulonglong2*)&xs[r][kg * 64];
#pragma unroll
            for (int i = 0; i < 16; i++) {
                ulonglong2 hv = xp[i];
                acc[r][0] = fma2(wa[2 * i],     hv.x, acc[r][0]);
                acc[r][0] = fma2(wa[2 * i + 1], hv.y, acc[r][0]);
                acc[r][1] = fma2(wb[2 * i],     hv.x, acc[r][1]);
                acc[r][1] = fma2(wb[2 * i + 1], hv.y, acc[r][1]);
            }
        }
#pragma unroll
        for (int r = 0; r < 8; r++) {
            pbuf[r * 512 + kg * 128 + og]      = f2sum(acc[r][0]);
            pbuf[r * 512 + kg * 128 + og + 64] = f2sum(acc[r][1]);
        }
        __syncthreads();
        if (it < 15) {
            int q = tid;
            ((float4*)xs)[q]       = n0;
            ((float4*)xs)[q + 256] = n1;
        }
        if (tid < 128) {
#pragma unroll
            for (int r = 0; r < 8; r++) {
                float s = pbuf[r * 512 + tid] + pbuf[r * 512 + 128 + tid] +
                          pbuf[r * 512 + 256 + tid] + pbuf[r * 512 + 384 + tid] + bias;
                g_xw[(size_t)(rowbase + r) * NH + half * 128 + tid] = s;
            }
        }
        __syncthreads();
    }
}

// =================================================================
// Kernel 2: persistent recurrence, v3.
//   64 clusters x 2 CTAs x 256 thr. CTA c owns output cols [c*128, +128).
//   Lane (w, l): cols j0 = c*128 + w*16 + (l&3)*4 .. +4, k-window [ (l>>2)*32, +32 ).
//   Weights (4 cols x 32 k = 128 f32) register-resident, permuted to the
//   XOR-swizzled h-buffer layout. Reduce over 8 k-parts via 3x shfl.xor.
//   Sync: per-buffer local mbarrier (32 STS arrives) + remote mbarrier
//   (512B complete_tx from peer's st.async). No __syncthreads in the loop.
// =================================================================
__global__ void __launch_bounds__(256, 1) __cluster_dims__(2, 1, 1)
rnn_kernel(const float* __restrict__ w_hh, float* __restrict__ out) {
    __shared__ __align__(16) float hbuf[2][256];          // XOR-swizzled
    __shared__ __align__(8) unsigned long long lbar[2];   // local-half ready
    __shared__ __align__(8) unsigned long long rbar[2];   // remote-half ready

    const int tid  = threadIdx.x;
    const int w    = tid >> 5, l = tid & 31;
    const int cg   = l & 3,  kp = l >> 2;          // col-group 0..3, k-part 0..7
    const int b    = blockIdx.x >> 1;
    const int c    = blockIdx.x & 1;
    const int peer = c ^ 1;
    const int j0   = c * 128 + w * 16 + cg * 4;    // 4 output cols (global)
    const int k0   = kp * 32;                      // k window (global)
    const bool is_local = ((kp >> 2) == c);        // window in own CTA's h half
    const bool writer   = (kp == 0);
    const bool poster   = (tid == (c == 0 ? 16 : 0));   // one REMOTE lane

    // --- register-resident weights, permuted to physical (swizzled) read order
    unsigned long long wreg[4][16];
#pragma unroll
    for (int cc = 0; cc < 4; cc++) {
        const unsigned long long* wr =
            (const unsigned long long*)(w_hh + (size_t)(j0 + cc) * NH);
#pragma unroll
        for (int i = 0; i < 8; i++) {
            int kb = (k0 + ((i ^ kp) << 2)) >> 1;   // u64 index into row
            wreg[cc][2 * i]     = wr[kb];
            wreg[cc][2 * i + 1] = wr[kb + 1];
        }
    }

    // writer's store slot: logical chunk -> physical (swizzle: ^bits[7:5]->[4:2])
    const int lch  = j0 >> 2;
    const int pch  = lch ^ ((lch >> 3) & 7);

    hbuf[0][tid] = 0.f;                            // h0 = 0 (swizzle-invariant)
    const uint32_t lb0 = smem_u32(&lbar[0]), lb1 = smem_u32(&lbar[1]);
    const uint32_t rb0 = smem_u32(&rbar[0]), rb1 = smem_u32(&rbar[1]);
    if (tid == 0) {
        mbar_init(lb0, 32); mbar_init(lb1, 32);    // 32 writer arrives / phase
        mbar_init(rb0, 1);  mbar_init(rb1, 1);     // 1 expect-arrive + 512B tx
    }
    // peer-side addresses
    const uint32_t phb0 = mapa_(smem_u32(&hbuf[0][0]), peer);
    const uint32_t phb1 = mapa_(smem_u32(&hbuf[1][0]), peer);
    const uint32_t prb0 = mapa_(rb0, peer);
    const uint32_t prb1 = mapa_(rb1, peer);

    __syncthreads();
    if (poster) mbar_expect(rb1, 512);             // h(1) phase, before any push
    cluster_sync_();                               // init + zeros cluster-visible

    float4 xc, x1, x2;
    if (writer) {
        xc = *(const float4*)&g_xw[(size_t)b * NH + j0];
        x1 = *(const float4*)&g_xw[((size_t)NB + b) * NH + j0];
    }

    int ph0 = 0, ph1 = 0;                          // per-barrier-slot parities
    for (int s = 0; s < T_SEQ; s++) {
        const int p = s & 1, q = p ^ 1;
        if (writer && s + 2 < T_SEQ)
            x2 = *(const float4*)&g_xw[((size_t)(s + 2) * NB + b) * NH + j0];

        // ---- wait h(s): each lane waits exactly one barrier ----
        if (s > 0) {
            uint32_t bar = is_local ? (p ? lb1 : lb0) : (p ? rb1 : rb0);
            int par = p ? ph1 : ph0;
            mbar_wait(bar, par);
            if (p) ph1 ^= 1; else ph0 ^= 1;
        }
        // re-arm remote barrier for h(s+2) (poster is a remote lane: it has
        // observed this slot's previous phase completion via its own wait)
        if (poster && s <= T_SEQ - 3) mbar_expect(p ? rb1 : rb0, 512);

        // ---- GEMV slice: 4 cols x 32 k  (64 fma2, 8 LDS.128) ----
        const ulonglong2* hp = (const ulonglong2*)&hbuf[p][k0];
        unsigned long long a0 = 0ull, a1 = 0ull, a2 = 0ull, a3 = 0ull;
#pragma unroll
        for (int i = 0; i < 8; i++) {
            ulonglong2 hv = hp[i];
            a0 = fma2(wreg[0][2 * i], hv.x, a0);
            a0 = fma2(wreg[0][2 * i + 1], hv.y, a0);
            a1 = fma2(wreg[1][2 * i], hv.x, a1);
            a1 = fma2(wreg[1][2 * i + 1], hv.y, a1);
            a2 = fma2(wreg[2][2 * i], hv.x, a2);
            a2 = fma2(wreg[2][2 * i + 1], hv.y, a2);
            a3 = fma2(wreg[3][2 * i], hv.x, a3);
            a3 = fma2(wreg[3][2 * i + 1], hv.y, a3);
        }
        float v0 = f2sum(a0), v1 = f2sum(a1), v2 = f2sum(a2), v3 = f2sum(a3);
#pragma unroll
        for (int d = 4; d <= 16; d <<= 1) {       // reduce over 8 k-parts
            v0 += __shfl_xor_sync(0xffffffffu, v0, d);
            v1 += __shfl_xor_sync(0xffffffffu, v1, d);
            v2 += __shfl_xor_sync(0xffffffffu, v2, d);
            v3 += __shfl_xor_sync(0xffffffffu, v3, d);
        }

        if (writer) {
            v0 = tanhf(v0 + xc.x);
            v1 = tanhf(v1 + xc.y);
            v2 = tanhf(v2 + xc.z);
            v3 = tanhf(v3 + xc.w);
            ((float4*)(out + ((size_t)s * NB + b) * NH))[lch] =
                make_float4(v0, v1, v2, v3);
            if (s + 1 < T_SEQ) {
                // local half: plain STS + arrive
                ((float4*)hbuf[q])[pch] = make_float4(v0, v1, v2, v3);
                // remote half: async push with tx-signal on peer's rbar[q]
                uint32_t pdst = (q ? phb1 : phb0) + (uint32_t)pch * 16u;
                uint32_t pbar = q ? prb1 : prb0;
                st_async_b64(pdst,     packf2(v0, v1), pbar);
                st_async_b64(pdst + 8, packf2(v2, v3), pbar);
                mbar_arrive(q ? lb1 : lb0);
            }
            xc = x1; x1 = x2;
        }
    }
    cluster_sync_();   // don't exit while peer's st.async may target our smem
}

// =================================================================
extern "C" void kernel_launch(void* const* d_in, const int* in_sizes, int n_in,
                              void* d_out, int out_size) {
    const float* x    = (const float*)d_in[0];
    const float* w_ih = (const float*)d_in[1];
    const float* w_hh = (const float*)d_in[2];
    const float* b_ih = (const float*)d_in[3];
    const float* b_hh = (const float*)d_in[4];
    float* out = (float*)d_out;

    dim3 g1(1024, 2);
    xw_kernel<<<g1, 256>>>(x, w_ih, b_ih, b_hh);
    rnn_kernel<<<128, 256>>>(w_hh, out);
}